// round 6
// baseline (speedup 1.0000x reference)
#include <cuda_runtime.h>
#include <cuda_bf16.h>
#include <cstdint>

// Problem constants (shapes are fixed by the dataset)
#define MAX_N 100000
#define MAX_E 1000000
#define MAX_TOT (MAX_N + MAX_E)

// Scratch: __device__ globals (no runtime allocation allowed)
__device__ float g_xl[MAX_N * 128];      // raw @ Wl
__device__ float g_xr[MAX_N * 128];      // raw @ Wr
__device__ float g_skip[MAX_N * 128];    // raw @ Ws + bs
__device__ float g_agg[MAX_N * 128];     // segment_sum(ee * xl[src])  (unnormalized)
__device__ float g_denom[MAX_N * 8];     // softmax denominators per head
__device__ int   g_is64;                 // edge_index dtype flag (1 = int64)
// W^T in bf16 hi/lo split, padded [n][k] layout (stride 136), 3 matrices
__device__ __nv_bfloat16 g_Bth[3 * 128 * 136];
__device__ __nv_bfloat16 g_Btl[3 * 128 * 136];

// ===================== PTX helpers (base ISA only) =========================
__device__ __forceinline__ uint32_t smem_u32(const void* p) {
    uint32_t a;
    asm("{ .reg .u64 t; cvta.to.shared.u64 t, %1; cvt.u32.u64 %0, t; }"
        : "=r"(a) : "l"(p));
    return a;
}
#define LDSM_X4(r0, r1, r2, r3, addr) \
    asm volatile("ldmatrix.sync.aligned.m8n8.x4.shared.b16 {%0,%1,%2,%3}, [%4];" \
                 : "=r"(r0), "=r"(r1), "=r"(r2), "=r"(r3) : "r"(addr))
#define MMA_BF16(d, a, b) \
    asm volatile("mma.sync.aligned.m16n8k16.row.col.f32.bf16.bf16.f32 " \
                 "{%0,%1,%2,%3}, {%4,%5,%6,%7}, {%8,%9}, {%0,%1,%2,%3};" \
                 : "+f"((d)[0]), "+f"((d)[1]), "+f"((d)[2]), "+f"((d)[3]) \
                 : "r"((a)[0]), "r"((a)[1]), "r"((a)[2]), "r"((a)[3]), \
                   "r"((b)[0]), "r"((b)[1]))

// ======================= misc small kernels ================================
__global__ void k_detect(const unsigned int* __restrict__ p) {
    unsigned int v = 0;
    for (int i = threadIdx.x; i < 128; i += 32) v |= p[2 * i + 1];
    v |= __shfl_xor_sync(0xffffffffu, v, 16);
    v |= __shfl_xor_sync(0xffffffffu, v, 8);
    v |= __shfl_xor_sync(0xffffffffu, v, 4);
    v |= __shfl_xor_sync(0xffffffffu, v, 2);
    v |= __shfl_xor_sync(0xffffffffu, v, 1);
    if (threadIdx.x == 0) g_is64 = (v == 0u) ? 1 : 0;
}

__device__ __forceinline__ void load_edge(const void* ei, int w, int E, int n,
                                          int& s, int& d) {
    if (w < E) {
        if (g_is64) {
            const long long* e = (const long long*)ei;
            s = (int)e[w]; d = (int)e[E + w];
        } else {
            const int* e = (const int*)ei;
            s = e[w]; d = e[E + w];
        }
        s = min(max(s, 0), n - 1);
        d = min(max(d, 0), n - 1);
    } else {
        s = d = w - E;  // self-loop
    }
}

__global__ void k_zero(int n) {
    int i = blockIdx.x * blockDim.x + threadIdx.x;
    const float4 z = make_float4(0.f, 0.f, 0.f, 0.f);
    int nAgg = n * 32;
    if (i < nAgg) {
        reinterpret_cast<float4*>(g_agg)[i] = z;
    } else if (i < nAgg + n * 2) {
        reinterpret_cast<float4*>(g_denom)[i - nAgg] = z;
    }
}

// ---------------------------------------------------------------------------
// Prep: W^T (=Bt[n][k]) in bf16 hi/lo, row stride 136 (ldmatrix-friendly).
// ---------------------------------------------------------------------------
__global__ void k_prep(const float* __restrict__ Wl, const float* __restrict__ Wr,
                       const float* __restrict__ Ws) {
    int i = blockIdx.x * blockDim.x + threadIdx.x;
    if (i >= 3 * 16384) return;
    int m = i >> 14, kk = (i >> 7) & 127, nn = i & 127;
    const float* W = (m == 0) ? Wl : ((m == 1) ? Wr : Ws);
    float v = W[kk * 128 + nn];
    __nv_bfloat16 h = __float2bfloat16(v);
    __nv_bfloat16 l = __float2bfloat16(v - __bfloat162float(h));
    g_Bth[m * 17408 + nn * 136 + kk] = h;
    g_Btl[m * 17408 + nn * 136 + kk] = l;
}

// ---------------------------------------------------------------------------
// Tensor-core GEMM via mma.sync bf16 split:  out = concat(x,tf) @ W
// Block: 128 rows x 128 cols, 256 threads (8 warps = 4 m x 2 n).
// Warp tile: 32 rows x 64 cols.  D = Ah*Bh + Ah*Bl + Al*Bh (fp32 acc).
// smem: A hi/lo + Bt hi/lo, all [128][136] bf16 (conflict-free ldmatrix).
// ---------------------------------------------------------------------------
#define SM_AH 0
#define SM_AL 34816
#define SM_BH 69632
#define SM_BL 104448
#define SM_TOTAL 139264

__global__ void __launch_bounds__(256, 1)
k_gemm_mma(const float* __restrict__ x, const float* __restrict__ tf,
           const float* __restrict__ bs, int n) {
    extern __shared__ char smem[];
    const uint32_t sbase = smem_u32(smem);
    const int tid = threadIdx.x;
    const int which = blockIdx.y;
    const int row0 = blockIdx.x * 128;
    float* out = (which == 0) ? g_xl : ((which == 1) ? g_xr : g_skip);

    // Copy Bt images (L2-resident) to smem: byte copy preserves layout
    {
        const uint4* gh = reinterpret_cast<const uint4*>(&g_Bth[which * 17408]);
        const uint4* gl = reinterpret_cast<const uint4*>(&g_Btl[which * 17408]);
        uint4* sh = reinterpret_cast<uint4*>(smem + SM_BH);
        uint4* sl = reinterpret_cast<uint4*>(smem + SM_BL);
        for (int i = tid; i < 2176; i += 256) { sh[i] = gh[i]; sl[i] = gl[i]; }
    }
    // Load A rows (fp32, coalesced), split to bf16 hi/lo
    {
        __nv_bfloat16* sh = reinterpret_cast<__nv_bfloat16*>(smem + SM_AH);
        __nv_bfloat16* sl = reinterpret_cast<__nv_bfloat16*>(smem + SM_AL);
        for (int i = tid; i < 128 * 128; i += 256) {
            int r = i >> 7, k = i & 127;
            int g = row0 + r;
            float v = 0.f;
            if (g < n) v = (k < 126) ? x[g * 126 + k] : tf[g * 2 + (k - 126)];
            __nv_bfloat16 h = __float2bfloat16(v);
            __nv_bfloat16 l = __float2bfloat16(v - __bfloat162float(h));
            sh[r * 136 + k] = h;
            sl[r * 136 + k] = l;
        }
    }
    __syncthreads();

    const int wid = tid >> 5;
    const int lane = tid & 31;
    const int wm = wid >> 1;          // 0..3 -> rows wm*32
    const int wn = wid & 1;           // 0..1 -> cols wn*64
    const int r0 = wm * 32;
    const int c0 = wn * 64;
    const int sub = lane >> 3;        // ldmatrix matrix index
    const int rin = lane & 7;         // row within 8x8 matrix

    float acc[2][8][4];
#pragma unroll
    for (int mt = 0; mt < 2; mt++)
#pragma unroll
        for (int nt = 0; nt < 8; nt++)
#pragma unroll
            for (int q = 0; q < 4; q++) acc[mt][nt][q] = 0.f;

    for (int ks = 0; ks < 8; ks++) {
        const int k0 = ks * 16;
        uint32_t ah[2][4], al[2][4], bh[8][2], bl[8][2];

        // A fragments: m0=rows0-7/k0-7, m1=rows8-15/k0-7, m2=rows0-7/k8-15, m3=rows8-15/k8-15
#pragma unroll
        for (int mt = 0; mt < 2; mt++) {
            const int row = r0 + mt * 16 + (sub & 1) * 8 + rin;
            const int col = k0 + (sub >> 1) * 8;
            const uint32_t off = (uint32_t)(row * 136 + col) * 2;
            LDSM_X4(ah[mt][0], ah[mt][1], ah[mt][2], ah[mt][3], sbase + SM_AH + off);
            LDSM_X4(al[mt][0], al[mt][1], al[mt][2], al[mt][3], sbase + SM_AL + off);
        }
        // B fragments (two n8 tiles per x4):
        // m0=nlow/k0-7, m1=nlow/k8-15, m2=nhigh/k0-7, m3=nhigh/k8-15
#pragma unroll
        for (int nt2 = 0; nt2 < 4; nt2++) {
            const int nn = c0 + nt2 * 16 + (sub >> 1) * 8 + rin;
            const int col = k0 + (sub & 1) * 8;
            const uint32_t off = (uint32_t)(nn * 136 + col) * 2;
            uint32_t q0, q1, q2, q3;
            LDSM_X4(q0, q1, q2, q3, sbase + SM_BH + off);
            bh[nt2 * 2][0] = q0;     bh[nt2 * 2][1] = q1;
            bh[nt2 * 2 + 1][0] = q2; bh[nt2 * 2 + 1][1] = q3;
            LDSM_X4(q0, q1, q2, q3, sbase + SM_BL + off);
            bl[nt2 * 2][0] = q0;     bl[nt2 * 2][1] = q1;
            bl[nt2 * 2 + 1][0] = q2; bl[nt2 * 2 + 1][1] = q3;
        }
        // 48 mma: 2 m-tiles x 8 n-tiles x 3 products
#pragma unroll
        for (int mt = 0; mt < 2; mt++)
#pragma unroll
            for (int nt = 0; nt < 8; nt++) {
                MMA_BF16(acc[mt][nt], ah[mt], bh[nt]);
                MMA_BF16(acc[mt][nt], ah[mt], bl[nt]);
                MMA_BF16(acc[mt][nt], al[mt], bh[nt]);
            }
    }

    // Epilogue: lane l -> rows r0+mt*16+(l>>2)(+8), cols c0+nt*8+(l&3)*2
#pragma unroll
    for (int mt = 0; mt < 2; mt++) {
#pragma unroll
        for (int nt = 0; nt < 8; nt++) {
            const int col = c0 + nt * 8 + (lane & 3) * 2;
            float b0 = 0.f, b1 = 0.f;
            if (which == 2) { b0 = bs[col]; b1 = bs[col + 1]; }
            const int ra = row0 + r0 + mt * 16 + (lane >> 2);
            if (ra < n) {
                float2 v = make_float2(acc[mt][nt][0] + b0, acc[mt][nt][1] + b1);
                *reinterpret_cast<float2*>(&out[ra * 128 + col]) = v;
            }
            const int rb = ra + 8;
            if (rb < n) {
                float2 v = make_float2(acc[mt][nt][2] + b0, acc[mt][nt][3] + b1);
                *reinterpret_cast<float2*>(&out[rb * 128 + col]) = v;
            }
        }
    }
}

// ---------------------------------------------------------------------------
// Fused edge pass, one edge per HALF-warp (unchanged from R4)
// ---------------------------------------------------------------------------
__global__ void k_edge(const void* __restrict__ ei,
                       const float* __restrict__ att, int E, int n) {
    const int gt = blockIdx.x * blockDim.x + threadIdx.x;
    const int w = gt >> 4;
    const int hl = threadIdx.x & 15;
    if (w >= E + n) return;

    int s, d;
    load_edge(ei, w, E, n, s, d);

    const float4 a0 = *reinterpret_cast<const float4*>(&g_xl[s * 128 + hl * 8]);
    const float4 a1 = *reinterpret_cast<const float4*>(&g_xl[s * 128 + hl * 8 + 4]);
    const float4 b0 = *reinterpret_cast<const float4*>(&g_xr[d * 128 + hl * 8]);
    const float4 b1 = *reinterpret_cast<const float4*>(&g_xr[d * 128 + hl * 8 + 4]);
    const float4 t0 = *reinterpret_cast<const float4*>(&att[hl * 8]);
    const float4 t1 = *reinterpret_cast<const float4*>(&att[hl * 8 + 4]);

    float m, p = 0.f;
    m = a0.x + b0.x; p += (m > 0.f ? m : 0.2f * m) * t0.x;
    m = a0.y + b0.y; p += (m > 0.f ? m : 0.2f * m) * t0.y;
    m = a0.z + b0.z; p += (m > 0.f ? m : 0.2f * m) * t0.z;
    m = a0.w + b0.w; p += (m > 0.f ? m : 0.2f * m) * t0.w;
    m = a1.x + b1.x; p += (m > 0.f ? m : 0.2f * m) * t1.x;
    m = a1.y + b1.y; p += (m > 0.f ? m : 0.2f * m) * t1.y;
    m = a1.z + b1.z; p += (m > 0.f ? m : 0.2f * m) * t1.z;
    m = a1.w + b1.w; p += (m > 0.f ? m : 0.2f * m) * t1.w;

    p += __shfl_xor_sync(0xffffffffu, p, 1);

    const float ex = expf(p);   // softmax-max dropped: |e| bounded (rel_err 7e-8)

    if ((hl & 1) == 0) {
        atomicAdd(&g_denom[d * 8 + (hl >> 1)], ex);
    }

    float4 v0 = a0, v1 = a1;
    v0.x *= ex; v0.y *= ex; v0.z *= ex; v0.w *= ex;
    v1.x *= ex; v1.y *= ex; v1.z *= ex; v1.w *= ex;
    float* p0 = &g_agg[d * 128 + hl * 8];
    float* p1 = &g_agg[d * 128 + hl * 8 + 4];
    asm volatile("red.global.add.v4.f32 [%0], {%1, %2, %3, %4};"
                 :: "l"(p0), "f"(v0.x), "f"(v0.y), "f"(v0.z), "f"(v0.w) : "memory");
    asm volatile("red.global.add.v4.f32 [%0], {%1, %2, %3, %4};"
                 :: "l"(p1), "f"(v1.x), "f"(v1.y), "f"(v1.z), "f"(v1.w) : "memory");
}

// ---------------------------------------------------------------------------
// Final: out = sigmoid( elu(agg/denom + bias_gat + skip) @ Wo + bo )
// ---------------------------------------------------------------------------
__global__ void k_final(const float* __restrict__ bias_gat,
                        const float* __restrict__ Wo,
                        const float* __restrict__ bo,
                        float* __restrict__ out, int n) {
    const int w = (blockIdx.x * blockDim.x + threadIdx.x) >> 5;
    const int lane = threadIdx.x & 31;
    if (w >= n) return;

    const int base = w * 128 + lane * 4;
    const float4 g  = *reinterpret_cast<const float4*>(&g_agg[base]);
    const float4 s  = *reinterpret_cast<const float4*>(&g_skip[base]);
    const float4 bg = *reinterpret_cast<const float4*>(&bias_gat[lane * 4]);
    const float4 ww = *reinterpret_cast<const float4*>(&Wo[lane * 4]);

    const float dn = 1.f / (g_denom[w * 8 + (lane >> 2)] + 1e-16f);

    float c, p = 0.f;
    c = g.x * dn + s.x + bg.x; c = (c > 0.f) ? c : expm1f(c); p += c * ww.x;
    c = g.y * dn + s.y + bg.y; c = (c > 0.f) ? c : expm1f(c); p += c * ww.y;
    c = g.z * dn + s.z + bg.z; c = (c > 0.f) ? c : expm1f(c); p += c * ww.z;
    c = g.w * dn + s.w + bg.w; c = (c > 0.f) ? c : expm1f(c); p += c * ww.w;

    p += __shfl_xor_sync(0xffffffffu, p, 16);
    p += __shfl_xor_sync(0xffffffffu, p, 8);
    p += __shfl_xor_sync(0xffffffffu, p, 4);
    p += __shfl_xor_sync(0xffffffffu, p, 2);
    p += __shfl_xor_sync(0xffffffffu, p, 1);

    if (lane == 0) {
        out[w] = 1.f / (1.f + expf(-(p + bo[0])));
    }
}

// ---------------------------------------------------------------------------
extern "C" void kernel_launch(void* const* d_in, const int* in_sizes, int n_in,
                              void* d_out, int out_size) {
    const float* x   = (const float*)d_in[0];   // [N,126]
    const float* tf  = (const float*)d_in[1];   // [N,2]
    const void*  ei  = d_in[2];                 // [2,E] int32 or int64
    const float* Wl  = (const float*)d_in[3];   // [128,128]
    const float* Wr  = (const float*)d_in[4];
    const float* att = (const float*)d_in[5];   // [8,16]
    const float* bg  = (const float*)d_in[6];   // [128]
    const float* Ws  = (const float*)d_in[7];
    const float* bs  = (const float*)d_in[8];
    const float* Wo  = (const float*)d_in[9];   // [128,1]
    const float* bo  = (const float*)d_in[10];  // [1]
    float* out = (float*)d_out;

    const int n = in_sizes[0] / 126;
    const int E = in_sizes[2] / 2;
    const int tot = E + n;

    cudaFuncSetAttribute(k_gemm_mma, cudaFuncAttributeMaxDynamicSharedMemorySize,
                         SM_TOTAL);

    k_detect<<<1, 32>>>((const unsigned int*)ei);
    k_zero<<<(n * 34 + 255) / 256, 256>>>(n);
    k_prep<<<(3 * 16384 + 255) / 256, 256>>>(Wl, Wr, Ws);

    dim3 gg((n + 127) / 128, 3);
    k_gemm_mma<<<gg, 256, SM_TOTAL>>>(x, tf, bs, n);

    k_edge<<<(tot + 15) / 16, 256>>>(ei, att, E, n);
    k_final<<<(n + 7) / 8, 256>>>(bg, Wo, bo, out, n);
}

// round 8
// speedup vs baseline: 1.9232x; 1.9232x over previous
#include <cuda_runtime.h>
#include <cuda_bf16.h>
#include <cstdint>

// Problem constants (shapes are fixed by the dataset)
#define MAX_N 100000
#define MAX_E 1000000
#define MAX_TOT (MAX_N + MAX_E)

// Scratch: __device__ globals (no runtime allocation allowed)
__device__ float g_xl[MAX_N * 128];      // raw @ Wl
__device__ float g_xr[MAX_N * 128];      // raw @ Wr
__device__ float g_skip[MAX_N * 128];    // raw @ Ws + bs
__device__ float g_agg[MAX_N * 128];     // segment_sum(ee * xl[src])  (unnormalized)
__device__ float g_denom[MAX_N * 8];     // softmax denominators per head
__device__ int   g_is64;                 // edge_index dtype flag (1 = int64)
// W^T in bf16 hi/lo split, XOR-swizzled [n][128] layout, 3 matrices
__device__ __nv_bfloat16 g_Bth[3 * 128 * 128];
__device__ __nv_bfloat16 g_Btl[3 * 128 * 128];

// ===================== PTX helpers (base ISA only) =========================
__device__ __forceinline__ uint32_t smem_u32(const void* p) {
    uint32_t a;
    asm("{ .reg .u64 t; cvta.to.shared.u64 t, %1; cvt.u32.u64 %0, t; }"
        : "=r"(a) : "l"(p));
    return a;
}
#define LDSM_X4(r0, r1, r2, r3, addr) \
    asm volatile("ldmatrix.sync.aligned.m8n8.x4.shared.b16 {%0,%1,%2,%3}, [%4];" \
                 : "=r"(r0), "=r"(r1), "=r"(r2), "=r"(r3) : "r"(addr))
#define MMA_BF16(d, a, b) \
    asm volatile("mma.sync.aligned.m16n8k16.row.col.f32.bf16.bf16.f32 " \
                 "{%0,%1,%2,%3}, {%4,%5,%6,%7}, {%8,%9}, {%0,%1,%2,%3};" \
                 : "+f"((d)[0]), "+f"((d)[1]), "+f"((d)[2]), "+f"((d)[3]) \
                 : "r"((a)[0]), "r"((a)[1]), "r"((a)[2]), "r"((a)[3]), \
                   "r"((b)[0]), "r"((b)[1]))

// XOR-swizzled halfword index within a [rows][128] bf16 tile (row stride 256B).
// chunk = k>>3 in 0..15; swizzled chunk keeps the high bit and XORs the low
// 3 bits with (r&7)  ->  bijective AND ldmatrix conflict-free.
__device__ __forceinline__ int swz(int r, int k) {
    int c = k >> 3;
    int sc = (c & 8) | ((c ^ r) & 7);
    return r * 128 + sc * 8 + (k & 7);
}

// ======================= misc small kernels ================================
__global__ void k_detect(const unsigned int* __restrict__ p) {
    unsigned int v = 0;
    for (int i = threadIdx.x; i < 128; i += 32) v |= p[2 * i + 1];
    v |= __shfl_xor_sync(0xffffffffu, v, 16);
    v |= __shfl_xor_sync(0xffffffffu, v, 8);
    v |= __shfl_xor_sync(0xffffffffu, v, 4);
    v |= __shfl_xor_sync(0xffffffffu, v, 2);
    v |= __shfl_xor_sync(0xffffffffu, v, 1);
    if (threadIdx.x == 0) g_is64 = (v == 0u) ? 1 : 0;
}

__device__ __forceinline__ void load_edge(const void* ei, int w, int E, int n,
                                          int& s, int& d) {
    if (w < E) {
        if (g_is64) {
            const long long* e = (const long long*)ei;
            s = (int)e[w]; d = (int)e[E + w];
        } else {
            const int* e = (const int*)ei;
            s = e[w]; d = e[E + w];
        }
        s = min(max(s, 0), n - 1);
        d = min(max(d, 0), n - 1);
    } else {
        s = d = w - E;  // self-loop
    }
}

__global__ void k_zero(int n) {
    int i = blockIdx.x * blockDim.x + threadIdx.x;
    const float4 z = make_float4(0.f, 0.f, 0.f, 0.f);
    int nAgg = n * 32;
    if (i < nAgg) {
        reinterpret_cast<float4*>(g_agg)[i] = z;
    } else if (i < nAgg + n * 2) {
        reinterpret_cast<float4*>(g_denom)[i - nAgg] = z;
    }
}

// ---------------------------------------------------------------------------
// Prep: W^T (=Bt[n][k]) in bf16 hi/lo, XOR-swizzled [128][128] tiles.
// ---------------------------------------------------------------------------
__global__ void k_prep(const float* __restrict__ Wl, const float* __restrict__ Wr,
                       const float* __restrict__ Ws) {
    int i = blockIdx.x * blockDim.x + threadIdx.x;
    if (i >= 3 * 16384) return;
    int m = i >> 14, kk = (i >> 7) & 127, nn = i & 127;
    const float* W = (m == 0) ? Wl : ((m == 1) ? Wr : Ws);
    float v = W[kk * 128 + nn];
    __nv_bfloat16 h = __float2bfloat16(v);
    __nv_bfloat16 l = __float2bfloat16(v - __bfloat162float(h));
    int idx = m * 16384 + swz(nn, kk);
    g_Bth[idx] = h;
    g_Btl[idx] = l;
}

// ---------------------------------------------------------------------------
// Tensor-core GEMM via mma.sync bf16 split:  {xl,xr,skip} = concat(x,tf) @ W*
// Block: 64 rows x 128 cols, 256 threads (8 warps = 4 m x 2 n), looping over
// all 3 weight matrices (A staged once).  Warp tile 16 rows x 64 cols.
// D = Ah*Bh + Ah*Bl + Al*Bh (fp32 acc).  smem 96KB -> 2 blocks/SM.
// ---------------------------------------------------------------------------
#define SM_AH 0
#define SM_AL 16384
#define SM_BH 32768
#define SM_BL 65536
#define SM_TOTAL 98304

__global__ void __launch_bounds__(256, 2)
k_gemm_mma(const float* __restrict__ x, const float* __restrict__ tf,
           const float* __restrict__ bs, int n) {
    extern __shared__ char smem[];
    const uint32_t sbase = smem_u32(smem);
    const int tid = threadIdx.x;
    const int row0 = blockIdx.x * 64;

    // Stage A rows (fp32 coalesced) -> bf16 hi/lo, swizzled
    {
        __nv_bfloat16* sh = reinterpret_cast<__nv_bfloat16*>(smem + SM_AH);
        __nv_bfloat16* sl = reinterpret_cast<__nv_bfloat16*>(smem + SM_AL);
        for (int i = tid; i < 64 * 128; i += 256) {
            int r = i >> 7, k = i & 127;
            int g = row0 + r;
            float v = 0.f;
            if (g < n) v = (k < 126) ? x[g * 126 + k] : tf[g * 2 + (k - 126)];
            __nv_bfloat16 h = __float2bfloat16(v);
            __nv_bfloat16 l = __float2bfloat16(v - __bfloat162float(h));
            int idx = swz(r, k);
            sh[idx] = h;
            sl[idx] = l;
        }
    }

    const int wid = tid >> 5;
    const int lane = tid & 31;
    const int wm = wid >> 1;          // 0..3 -> rows wm*16
    const int wn = wid & 1;           // 0..1 -> cols wn*64
    const int r0 = wm * 16;
    const int c0 = wn * 64;
    const int sub = lane >> 3;        // ldmatrix matrix index
    const int rin = lane & 7;         // row within 8x8 matrix

    for (int which = 0; which < 3; which++) {
        float* out = (which == 0) ? g_xl : ((which == 1) ? g_xr : g_skip);

        // Copy swizzled Bt images (L2-hot) into smem — byte copy
        {
            const uint4* gh = reinterpret_cast<const uint4*>(&g_Bth[which * 16384]);
            const uint4* gl = reinterpret_cast<const uint4*>(&g_Btl[which * 16384]);
            uint4* sh = reinterpret_cast<uint4*>(smem + SM_BH);
            uint4* sl = reinterpret_cast<uint4*>(smem + SM_BL);
            for (int i = tid; i < 2048; i += 256) { sh[i] = gh[i]; sl[i] = gl[i]; }
        }
        __syncthreads();

        float acc[8][4];
#pragma unroll
        for (int nt = 0; nt < 8; nt++)
#pragma unroll
            for (int q = 0; q < 4; q++) acc[nt][q] = 0.f;

#pragma unroll
        for (int ks = 0; ks < 8; ks++) {
            uint32_t ah[4], al[4], bh[8][2], bl[8][2];

            // A fragment: matrix order {r0-7/k0-7, r8-15/k0-7, r0-7/k8-15, r8-15/k8-15}
            {
                const int ar = r0 + (sub & 1) * 8 + rin;
                const int ac = ks * 2 + (sub >> 1);           // 16B chunk index 0..15
                const uint32_t off =
                    (uint32_t)(ar * 256 + (((ac & 8) | ((ac ^ ar) & 7)) << 4));
                LDSM_X4(ah[0], ah[1], ah[2], ah[3], sbase + SM_AH + off);
                LDSM_X4(al[0], al[1], al[2], al[3], sbase + SM_AL + off);
            }
            // B fragments: per nt2 matrices {nlow/k0-7, nlow/k8-15, nhigh/k0-7, nhigh/k8-15}
#pragma unroll
            for (int nt2 = 0; nt2 < 4; nt2++) {
                const int br = c0 + nt2 * 16 + (sub >> 1) * 8 + rin;
                const int bc = ks * 2 + (sub & 1);
                const uint32_t off =
                    (uint32_t)(br * 256 + (((bc & 8) | ((bc ^ br) & 7)) << 4));
                uint32_t q0, q1, q2, q3;
                LDSM_X4(q0, q1, q2, q3, sbase + SM_BH + off);
                bh[nt2 * 2][0] = q0;     bh[nt2 * 2][1] = q1;
                bh[nt2 * 2 + 1][0] = q2; bh[nt2 * 2 + 1][1] = q3;
                LDSM_X4(q0, q1, q2, q3, sbase + SM_BL + off);
                bl[nt2 * 2][0] = q0;     bl[nt2 * 2][1] = q1;
                bl[nt2 * 2 + 1][0] = q2; bl[nt2 * 2 + 1][1] = q3;
            }
            // 24 mma: 8 n-tiles x 3 products
#pragma unroll
            for (int nt = 0; nt < 8; nt++) {
                MMA_BF16(acc[nt], ah, bh[nt]);
                MMA_BF16(acc[nt], ah, bl[nt]);
                MMA_BF16(acc[nt], al, bh[nt]);
            }
        }

        // Epilogue: lane l -> rows r0+(l>>2)(+8), cols c0+nt*8+(l&3)*2
#pragma unroll
        for (int nt = 0; nt < 8; nt++) {
            const int col = c0 + nt * 8 + (lane & 3) * 2;
            float b0 = 0.f, b1 = 0.f;
            if (which == 2) { b0 = bs[col]; b1 = bs[col + 1]; }
            const int ra = row0 + r0 + (lane >> 2);
            if (ra < n) {
                float2 v = make_float2(acc[nt][0] + b0, acc[nt][1] + b1);
                *reinterpret_cast<float2*>(&out[ra * 128 + col]) = v;
            }
            const int rb = ra + 8;
            if (rb < n) {
                float2 v = make_float2(acc[nt][2] + b0, acc[nt][3] + b1);
                *reinterpret_cast<float2*>(&out[rb * 128 + col]) = v;
            }
        }
        __syncthreads();   // B smem reused next iteration
    }
}

// ---------------------------------------------------------------------------
// Fused edge pass, one edge per HALF-warp (unchanged from R4)
// ---------------------------------------------------------------------------
__global__ void k_edge(const void* __restrict__ ei,
                       const float* __restrict__ att, int E, int n) {
    const int gt = blockIdx.x * blockDim.x + threadIdx.x;
    const int w = gt >> 4;
    const int hl = threadIdx.x & 15;
    if (w >= E + n) return;

    int s, d;
    load_edge(ei, w, E, n, s, d);

    const float4 a0 = *reinterpret_cast<const float4*>(&g_xl[s * 128 + hl * 8]);
    const float4 a1 = *reinterpret_cast<const float4*>(&g_xl[s * 128 + hl * 8 + 4]);
    const float4 b0 = *reinterpret_cast<const float4*>(&g_xr[d * 128 + hl * 8]);
    const float4 b1 = *reinterpret_cast<const float4*>(&g_xr[d * 128 + hl * 8 + 4]);
    const float4 t0 = *reinterpret_cast<const float4*>(&att[hl * 8]);
    const float4 t1 = *reinterpret_cast<const float4*>(&att[hl * 8 + 4]);

    float m, p = 0.f;
    m = a0.x + b0.x; p += (m > 0.f ? m : 0.2f * m) * t0.x;
    m = a0.y + b0.y; p += (m > 0.f ? m : 0.2f * m) * t0.y;
    m = a0.z + b0.z; p += (m > 0.f ? m : 0.2f * m) * t0.z;
    m = a0.w + b0.w; p += (m > 0.f ? m : 0.2f * m) * t0.w;
    m = a1.x + b1.x; p += (m > 0.f ? m : 0.2f * m) * t1.x;
    m = a1.y + b1.y; p += (m > 0.f ? m : 0.2f * m) * t1.y;
    m = a1.z + b1.z; p += (m > 0.f ? m : 0.2f * m) * t1.z;
    m = a1.w + b1.w; p += (m > 0.f ? m : 0.2f * m) * t1.w;

    p += __shfl_xor_sync(0xffffffffu, p, 1);

    const float ex = expf(p);   // softmax-max dropped: |e| bounded (rel_err 7e-8)

    if ((hl & 1) == 0) {
        atomicAdd(&g_denom[d * 8 + (hl >> 1)], ex);
    }

    float4 v0 = a0, v1 = a1;
    v0.x *= ex; v0.y *= ex; v0.z *= ex; v0.w *= ex;
    v1.x *= ex; v1.y *= ex; v1.z *= ex; v1.w *= ex;
    float* p0 = &g_agg[d * 128 + hl * 8];
    float* p1 = &g_agg[d * 128 + hl * 8 + 4];
    asm volatile("red.global.add.v4.f32 [%0], {%1, %2, %3, %4};"
                 :: "l"(p0), "f"(v0.x), "f"(v0.y), "f"(v0.z), "f"(v0.w) : "memory");
    asm volatile("red.global.add.v4.f32 [%0], {%1, %2, %3, %4};"
                 :: "l"(p1), "f"(v1.x), "f"(v1.y), "f"(v1.z), "f"(v1.w) : "memory");
}

// ---------------------------------------------------------------------------
// Final: out = sigmoid( elu(agg/denom + bias_gat + skip) @ Wo + bo )
// ---------------------------------------------------------------------------
__global__ void k_final(const float* __restrict__ bias_gat,
                        const float* __restrict__ Wo,
                        const float* __restrict__ bo,
                        float* __restrict__ out, int n) {
    const int w = (blockIdx.x * blockDim.x + threadIdx.x) >> 5;
    const int lane = threadIdx.x & 31;
    if (w >= n) return;

    const int base = w * 128 + lane * 4;
    const float4 g  = *reinterpret_cast<const float4*>(&g_agg[base]);
    const float4 s  = *reinterpret_cast<const float4*>(&g_skip[base]);
    const float4 bg = *reinterpret_cast<const float4*>(&bias_gat[lane * 4]);
    const float4 ww = *reinterpret_cast<const float4*>(&Wo[lane * 4]);

    const float dn = 1.f / (g_denom[w * 8 + (lane >> 2)] + 1e-16f);

    float c, p = 0.f;
    c = g.x * dn + s.x + bg.x; c = (c > 0.f) ? c : expm1f(c); p += c * ww.x;
    c = g.y * dn + s.y + bg.y; c = (c > 0.f) ? c : expm1f(c); p += c * ww.y;
    c = g.z * dn + s.z + bg.z; c = (c > 0.f) ? c : expm1f(c); p += c * ww.z;
    c = g.w * dn + s.w + bg.w; c = (c > 0.f) ? c : expm1f(c); p += c * ww.w;

    p += __shfl_xor_sync(0xffffffffu, p, 16);
    p += __shfl_xor_sync(0xffffffffu, p, 8);
    p += __shfl_xor_sync(0xffffffffu, p, 4);
    p += __shfl_xor_sync(0xffffffffu, p, 2);
    p += __shfl_xor_sync(0xffffffffu, p, 1);

    if (lane == 0) {
        out[w] = 1.f / (1.f + expf(-(p + bo[0])));
    }
}

// ---------------------------------------------------------------------------
extern "C" void kernel_launch(void* const* d_in, const int* in_sizes, int n_in,
                              void* d_out, int out_size) {
    const float* x   = (const float*)d_in[0];   // [N,126]
    const float* tf  = (const float*)d_in[1];   // [N,2]
    const void*  ei  = d_in[2];                 // [2,E] int32 or int64
    const float* Wl  = (const float*)d_in[3];   // [128,128]
    const float* Wr  = (const float*)d_in[4];
    const float* att = (const float*)d_in[5];   // [8,16]
    const float* bg  = (const float*)d_in[6];   // [128]
    const float* Ws  = (const float*)d_in[7];
    const float* bs  = (const float*)d_in[8];
    const float* Wo  = (const float*)d_in[9];   // [128,1]
    const float* bo  = (const float*)d_in[10];  // [1]
    float* out = (float*)d_out;

    const int n = in_sizes[0] / 126;
    const int E = in_sizes[2] / 2;
    const int tot = E + n;

    cudaFuncSetAttribute(k_gemm_mma, cudaFuncAttributeMaxDynamicSharedMemorySize,
                         SM_TOTAL);

    k_detect<<<1, 32>>>((const unsigned int*)ei);
    k_zero<<<(n * 34 + 255) / 256, 256>>>(n);
    k_prep<<<(3 * 16384 + 255) / 256, 256>>>(Wl, Wr, Ws);

    k_gemm_mma<<<(n + 63) / 64, 256, SM_TOTAL>>>(x, tf, bs, n);

    k_edge<<<(tot + 15) / 16, 256>>>(ei, att, E, n);
    k_final<<<(n + 7) / 8, 256>>>(bg, Wo, bo, out, n);
}